// round 1
// baseline (speedup 1.0000x reference)
#include <cuda_runtime.h>
#include <math.h>

#define NN 8192
#define DD 512
#define TILE 128
#define KC 16
#define NCHUNK 4
#define CHUNK_COLS (NN / NCHUNK)   // 2048

#define POS_INF  __int_as_float(0x7f800000)
#define NEG_INF  __int_as_float(0xff800000)

// ---- device scratch (no allocations allowed) ----
__device__ float g_unit[NN * DD];                 // 16 MB unit vectors
__device__ float g_posSim[NCHUNK][NN];
__device__ int   g_posIdx[NCHUNK][NN];
__device__ float g_negSim[NCHUNK][NN];
__device__ int   g_negIdx[NCHUNK][NN];
__device__ float g_per[NN];
__device__ float g_validf[NN];

// ============================================================
// Kernel 1: unit = emb / max(||emb||, 1e-8)   (one warp per row)
// ============================================================
__global__ void normalize_kernel(const float* __restrict__ emb) {
    int warp = (blockIdx.x * blockDim.x + threadIdx.x) >> 5;
    int lane = threadIdx.x & 31;
    if (warp >= NN) return;
    const float* row = emb + (size_t)warp * DD;
    float v[16];
    float ss = 0.f;
#pragma unroll
    for (int q = 0; q < 16; q++) {
        v[q] = row[lane + 32 * q];
        ss += v[q] * v[q];
    }
#pragma unroll
    for (int o = 16; o; o >>= 1) ss += __shfl_xor_sync(0xffffffffu, ss, o);
    float nrm = sqrtf(ss);
    float inv = 1.0f / fmaxf(nrm, 1e-8f);
#pragma unroll
    for (int q = 0; q < 16; q++)
        g_unit[(size_t)warp * DD + lane + 32 * q] = v[q] * inv;
}

// ============================================================
// Kernel 2: fused GEMM (unit @ unit^T) + masked hardest pos/neg
// 128x128 tile per block, 8x8 micro-tile per thread, 256 threads.
// Column space split into NCHUNK chunks (blockIdx.y).
// ============================================================
__global__ __launch_bounds__(256, 1)
void simtile_kernel(const int* __restrict__ labels) {
    __shared__ __align__(16) float As[2][KC][TILE];
    __shared__ __align__(16) float Bs[2][KC][TILE];
    __shared__ int Ls[TILE];

    const int i0    = blockIdx.x * TILE;
    const int chunk = blockIdx.y;
    const int j0base = chunk * CHUNK_COLS;
    const int t  = threadIdx.x;
    const int tx = t & 15;        // 0..15  -> cols tx*8..tx*8+7
    const int ty = t >> 4;        // 0..15  -> rows ty*8..ty*8+7

    int li[8];
#pragma unroll
    for (int a = 0; a < 8; a++) li[a] = labels[i0 + ty * 8 + a];

    float posS[8], negS[8];
    int   posI[8], negI[8];
#pragma unroll
    for (int a = 0; a < 8; a++) {
        posS[a] = POS_INF;  posI[a] = 0x7fffffff;
        negS[a] = NEG_INF;  negI[a] = 0x7fffffff;
    }

    const int NKT = DD / KC;   // 32 k-chunks

    for (int jt = 0; jt < CHUNK_COLS / TILE; jt++) {
        const int j0 = j0base + jt * TILE;

        __syncthreads();   // previous tile's smem/Ls consumers are done
        if (t < TILE) Ls[t] = labels[j0 + t];

        float acc[8][8];
#pragma unroll
        for (int a = 0; a < 8; a++)
#pragma unroll
            for (int b = 0; b < 8; b++) acc[a][b] = 0.f;

        // prefetch chunk 0 into regs
        float4 pa[2], pb[2];
#pragma unroll
        for (int q = 0; q < 2; q++) {
            int idx = q * 256 + t;
            int row = idx >> 2, f4 = idx & 3;
            pa[q] = *(const float4*)&g_unit[(size_t)(i0 + row) * DD + f4 * 4];
            pb[q] = *(const float4*)&g_unit[(size_t)(j0 + row) * DD + f4 * 4];
        }
        // store chunk 0 into smem buf 0
#pragma unroll
        for (int q = 0; q < 2; q++) {
            int idx = q * 256 + t;
            int row = idx >> 2, f4 = idx & 3;
            As[0][f4 * 4 + 0][row] = pa[q].x;
            As[0][f4 * 4 + 1][row] = pa[q].y;
            As[0][f4 * 4 + 2][row] = pa[q].z;
            As[0][f4 * 4 + 3][row] = pa[q].w;
            Bs[0][f4 * 4 + 0][row] = pb[q].x;
            Bs[0][f4 * 4 + 1][row] = pb[q].y;
            Bs[0][f4 * 4 + 2][row] = pb[q].z;
            Bs[0][f4 * 4 + 3][row] = pb[q].w;
        }
        __syncthreads();

        int buf = 0;
        for (int kc = 0; kc < NKT; kc++) {
            // prefetch next chunk while computing the current one
            if (kc + 1 < NKT) {
                int koff = (kc + 1) * KC;
#pragma unroll
                for (int q = 0; q < 2; q++) {
                    int idx = q * 256 + t;
                    int row = idx >> 2, f4 = idx & 3;
                    pa[q] = *(const float4*)&g_unit[(size_t)(i0 + row) * DD + koff + f4 * 4];
                    pb[q] = *(const float4*)&g_unit[(size_t)(j0 + row) * DD + koff + f4 * 4];
                }
            }
            // compute on smem[buf]
#pragma unroll
            for (int kk = 0; kk < KC; kk++) {
                float4 a0 = *(const float4*)&As[buf][kk][ty * 8];
                float4 a1 = *(const float4*)&As[buf][kk][ty * 8 + 4];
                float4 b0 = *(const float4*)&Bs[buf][kk][tx * 8];
                float4 b1 = *(const float4*)&Bs[buf][kk][tx * 8 + 4];
                float av[8] = {a0.x, a0.y, a0.z, a0.w, a1.x, a1.y, a1.z, a1.w};
                float bv[8] = {b0.x, b0.y, b0.z, b0.w, b1.x, b1.y, b1.z, b1.w};
#pragma unroll
                for (int a = 0; a < 8; a++)
#pragma unroll
                    for (int b = 0; b < 8; b++)
                        acc[a][b] = fmaf(av[a], bv[b], acc[a][b]);
            }
            // stage the prefetched chunk into the other buffer
            if (kc + 1 < NKT) {
                int nb = buf ^ 1;
#pragma unroll
                for (int q = 0; q < 2; q++) {
                    int idx = q * 256 + t;
                    int row = idx >> 2, f4 = idx & 3;
                    As[nb][f4 * 4 + 0][row] = pa[q].x;
                    As[nb][f4 * 4 + 1][row] = pa[q].y;
                    As[nb][f4 * 4 + 2][row] = pa[q].z;
                    As[nb][f4 * 4 + 3][row] = pa[q].w;
                    Bs[nb][f4 * 4 + 0][row] = pb[q].x;
                    Bs[nb][f4 * 4 + 1][row] = pb[q].y;
                    Bs[nb][f4 * 4 + 2][row] = pb[q].z;
                    Bs[nb][f4 * 4 + 3][row] = pb[q].w;
                }
                buf = nb;
                __syncthreads();
            }
        }

        // masked running selection. hardest positive = min sim among same
        // label (excl self); hardest negative = max sim among diff label.
        // Strict compares + ascending j order == JAX "first index wins".
#pragma unroll
        for (int a = 0; a < 8; a++) {
            int gi = i0 + ty * 8 + a;
            int la = li[a];
#pragma unroll
            for (int b = 0; b < 8; b++) {
                int gj = j0 + tx * 8 + b;
                float s = acc[a][b];
                int lj = Ls[tx * 8 + b];
                if (lj == la) {
                    if (gj != gi && s < posS[a]) { posS[a] = s; posI[a] = gj; }
                } else {
                    if (s > negS[a]) { negS[a] = s; negI[a] = gj; }
                }
            }
        }
    }

    // reduce across the 16 threads (tx) covering each row; tx group is a
    // half-warp so shfl_xor with offsets < 16 stays in-group.
#pragma unroll
    for (int a = 0; a < 8; a++) {
        float ps = posS[a]; int pi = posI[a];
        float ns = negS[a]; int ni = negI[a];
#pragma unroll
        for (int o = 8; o; o >>= 1) {
            float ops = __shfl_xor_sync(0xffffffffu, ps, o);
            int   opi = __shfl_xor_sync(0xffffffffu, pi, o);
            float ons = __shfl_xor_sync(0xffffffffu, ns, o);
            int   oni = __shfl_xor_sync(0xffffffffu, ni, o);
            if (ops < ps || (ops == ps && opi < pi)) { ps = ops; pi = opi; }
            if (ons > ns || (ons == ns && oni < ni)) { ns = ons; ni = oni; }
        }
        if (tx == 0) {
            int gi = i0 + ty * 8 + a;
            g_posSim[chunk][gi] = ps;  g_posIdx[chunk][gi] = pi;
            g_negSim[chunk][gi] = ns;  g_negIdx[chunk][gi] = ni;
        }
    }
}

// ============================================================
// Kernel 3: combine chunk partials, compute per-row triplet loss
// (one warp per row)
// ============================================================
__global__ void loss_kernel(const float* __restrict__ emb) {
    int warp = (blockIdx.x * blockDim.x + threadIdx.x) >> 5;
    int lane = threadIdx.x & 31;
    if (warp >= NN) return;
    int i = warp;

    float ps = g_posSim[0][i]; int pi = g_posIdx[0][i];
    float ns = g_negSim[0][i]; int ni = g_negIdx[0][i];
#pragma unroll
    for (int c = 1; c < NCHUNK; c++) {
        float cps = g_posSim[c][i]; int cpi = g_posIdx[c][i];
        float cns = g_negSim[c][i]; int cni = g_negIdx[c][i];
        // chunks are in ascending-j order: strict compare keeps first index
        if (cps < ps) { ps = cps; pi = cpi; }
        if (cns > ns) { ns = cns; ni = cni; }
    }
    bool hasP = (ps < POS_INF);
    bool hasN = (ns > NEG_INF);
    bool valid = hasP && hasN;
    if (!hasP) pi = 0;   // JAX argmax of all -1e9 -> 0 (masked by valid)
    if (!hasN) ni = 0;

    const float* a = emb + (size_t)i * DD;
    const float* p = emb + (size_t)pi * DD;
    const float* g = emb + (size_t)ni * DD;
    float sap = 0.f, san = 0.f;
#pragma unroll
    for (int q = 0; q < 16; q++) {
        int k = lane + 32 * q;
        float dap = a[k] - p[k] + 1e-6f;
        float dan = a[k] - g[k] + 1e-6f;
        sap = fmaf(dap, dap, sap);
        san = fmaf(dan, dan, san);
    }
#pragma unroll
    for (int o = 16; o; o >>= 1) {
        sap += __shfl_xor_sync(0xffffffffu, sap, o);
        san += __shfl_xor_sync(0xffffffffu, san, o);
    }
    if (lane == 0) {
        float per = fmaxf(sqrtf(sap) - sqrtf(san) + 1.0f, 0.0f);
        g_per[i]    = valid ? per : 0.0f;
        g_validf[i] = valid ? 1.0f : 0.0f;
    }
}

// ============================================================
// Kernel 4: deterministic final reduction
// ============================================================
__global__ void reduce_kernel(float* __restrict__ out) {
    __shared__ float s1[1024];
    __shared__ float s2[1024];
    int t = threadIdx.x;
    float a = 0.f, b = 0.f;
    for (int i = t; i < NN; i += 1024) { a += g_per[i]; b += g_validf[i]; }
    s1[t] = a; s2[t] = b;
    __syncthreads();
#pragma unroll
    for (int o = 512; o; o >>= 1) {
        if (t < o) { s1[t] += s1[t + o]; s2[t] += s2[t + o]; }
        __syncthreads();
    }
    if (t == 0) out[0] = s1[0] / fmaxf(s2[0], 1.0f);
}

// ============================================================
extern "C" void kernel_launch(void* const* d_in, const int* in_sizes, int n_in,
                              void* d_out, int out_size) {
    const float* emb   = (const float*)d_in[0];
    const int*   labels = (const int*)d_in[1];
    float* out = (float*)d_out;

    normalize_kernel<<<NN / 8, 256>>>(emb);                 // 8 warps/block
    dim3 grid(NN / TILE, NCHUNK);                           // 64 x 4
    simtile_kernel<<<grid, 256>>>(labels);
    loss_kernel<<<NN / 8, 256>>>(emb);
    reduce_kernel<<<1, 1024>>>(out);
}

// round 5
// speedup vs baseline: 4.5587x; 4.5587x over previous
#include <cuda_runtime.h>
#include <math.h>
#include <stdint.h>

#define NN 8192
#define DD 512
#define TMT 128                    // CTA tile M
#define TNT 128                    // CTA tile N
#define NCHUNK (NN / TNT)          // 64 column chunks
#define KC 32                      // K per pipeline chunk
#define NKC (DD / KC)              // 16

#define POS_INF  __int_as_float(0x7f800000)
#define NEG_INF  __int_as_float(0xff800000)

// smem layout (bytes)
#define S_LJ   0                   // 128 col labels
#define S_LI   512                 // 128 row labels
#define S_BUF  1024                // 2 x (A 16KB + B 16KB)
#define ABUF_BYTES (TMT * KC * 4)  // 16384
#define S_TOTAL (S_BUF + 2 * (2 * ABUF_BYTES))   // 66560
// epilogue overlays (reuse buffer region)
#define S_EPS  S_BUF               // float [4][128]
#define S_EPI  (S_BUF + 2048)      // int   [4][128]
#define S_ENS  (S_BUF + 4096)
#define S_ENI  (S_BUF + 6144)

// ---- device scratch ----
__device__ float g_unit[NN * DD];                 // tf32-rounded unit vectors
__device__ float g_posSim[NCHUNK][NN];
__device__ int   g_posIdx[NCHUNK][NN];
__device__ float g_negSim[NCHUNK][NN];
__device__ int   g_negIdx[NCHUNK][NN];
__device__ float g_per[NN];
__device__ float g_validf[NN];

__device__ __forceinline__ uint32_t smem_u32(const void* p) {
    uint32_t a;
    asm("{ .reg .u64 t; cvta.to.shared.u64 t, %1; cvt.u32.u64 %0, t; }" : "=r"(a) : "l"(p));
    return a;
}
#define CP_ASYNC16(dst, src) \
    asm volatile("cp.async.cg.shared.global [%0], [%1], 16;" :: "r"(dst), "l"(src))
#define CP_COMMIT() asm volatile("cp.async.commit_group;" ::: "memory")
#define CP_WAIT(n)  asm volatile("cp.async.wait_group %0;" :: "n"(n) : "memory")

__device__ __forceinline__ void mma_tf32(float* d, const uint32_t* a, const uint32_t* b) {
    asm volatile(
        "mma.sync.aligned.m16n8k8.row.col.f32.tf32.tf32.f32 "
        "{%0,%1,%2,%3}, {%4,%5,%6,%7}, {%8,%9}, {%0,%1,%2,%3};"
        : "+f"(d[0]), "+f"(d[1]), "+f"(d[2]), "+f"(d[3])
        : "r"(a[0]), "r"(a[1]), "r"(a[2]), "r"(a[3]), "r"(b[0]), "r"(b[1]));
}

// ============================================================
// Kernel 1: unit = tf32_round(emb / max(||emb||, 1e-8))
// ============================================================
__global__ void normalize_kernel(const float* __restrict__ emb) {
    int warp = (blockIdx.x * blockDim.x + threadIdx.x) >> 5;
    int lane = threadIdx.x & 31;
    if (warp >= NN) return;
    const float* row = emb + (size_t)warp * DD;
    float v[16];
    float ss = 0.f;
#pragma unroll
    for (int q = 0; q < 16; q++) { v[q] = row[lane + 32 * q]; ss += v[q] * v[q]; }
#pragma unroll
    for (int o = 16; o; o >>= 1) ss += __shfl_xor_sync(0xffffffffu, ss, o);
    float inv = 1.0f / fmaxf(sqrtf(ss), 1e-8f);
#pragma unroll
    for (int q = 0; q < 16; q++) {
        uint32_t u;
        asm("cvt.rna.tf32.f32 %0, %1;" : "=r"(u) : "f"(v[q] * inv));
        g_unit[(size_t)warp * DD + lane + 32 * q] = __uint_as_float(u);
    }
}

// ============================================================
// Kernel 2: tf32 mma.sync Gram tile (128x128) + fused hardest pos/neg
// ============================================================
__device__ __forceinline__ void load_chunk(char* smem, int buf,
                                           const float* Ab, const float* Bb,
                                           int kc, int t) {
    float* As = (float*)(smem + S_BUF + buf * 2 * ABUF_BYTES);
    float* Bs = As + TMT * KC;
#pragma unroll
    for (int p = 0; p < 4; p++) {
        int id = t + p * 256;
        int row = id >> 3, seg = id & 7;
        int dseg = seg ^ (row & 7);
        uint32_t dst = smem_u32(As + row * KC + dseg * 4);
        const char* src = (const char*)(Ab + (size_t)row * DD + kc * KC + seg * 4);
        CP_ASYNC16(dst, src);
    }
#pragma unroll
    for (int p = 0; p < 4; p++) {
        int id = t + p * 256;
        int row = id >> 3, seg = id & 7;
        int dseg = seg ^ (row & 7);
        uint32_t dst = smem_u32(Bs + row * KC + dseg * 4);
        const char* src = (const char*)(Bb + (size_t)row * DD + kc * KC + seg * 4);
        CP_ASYNC16(dst, src);
    }
    CP_COMMIT();
}

__global__ __launch_bounds__(256, 2)
void simtile_kernel(const int* __restrict__ labels) {
    extern __shared__ char smem[];
    const int t = threadIdx.x;
    const int wid = t >> 5, lane = t & 31;
    const int wm = wid >> 2;          // 0..1  (64 rows each)
    const int wn = wid & 3;           // 0..3  (32 cols each)
    const int g = lane >> 2, q = lane & 3;
    const int i0 = blockIdx.x * TMT;
    const int j0 = blockIdx.y * TNT;

    int* Lj = (int*)(smem + S_LJ);
    int* Li = (int*)(smem + S_LI);
    if (t < 128) { Lj[t] = labels[j0 + t]; Li[t] = labels[i0 + t]; }

    const float* Ab = g_unit + (size_t)i0 * DD;
    const float* Bb = g_unit + (size_t)j0 * DD;

    float acc[4][4][4];
#pragma unroll
    for (int mt = 0; mt < 4; mt++)
#pragma unroll
        for (int nt = 0; nt < 4; nt++)
#pragma unroll
            for (int e = 0; e < 4; e++) acc[mt][nt][e] = 0.f;

    load_chunk(smem, 0, Ab, Bb, 0, t);

    int buf = 0;
#pragma unroll 1
    for (int kc = 0; kc < NKC; kc++) {
        if (kc + 1 < NKC) load_chunk(smem, buf ^ 1, Ab, Bb, kc + 1, t);
        if (kc + 1 < NKC) { CP_WAIT(1); } else { CP_WAIT(0); }
        __syncthreads();

        const float* As = (const float*)(smem + S_BUF + buf * 2 * ABUF_BYTES);
        const float* Bs = As + TMT * KC;
#pragma unroll
        for (int ks8 = 0; ks8 < 4; ks8++) {
            const int w0 = ((2 * ks8 + 0) ^ g) * 4 + q;
            const int w1 = ((2 * ks8 + 1) ^ g) * 4 + q;
            uint32_t a[4][4], b[4][2];
#pragma unroll
            for (int mt = 0; mt < 4; mt++) {
                const float* b0 = As + (wm * 64 + mt * 16 + g) * KC;
                const float* b1 = b0 + 8 * KC;
                a[mt][0] = __float_as_uint(b0[w0]);
                a[mt][1] = __float_as_uint(b1[w0]);
                a[mt][2] = __float_as_uint(b0[w1]);
                a[mt][3] = __float_as_uint(b1[w1]);
            }
#pragma unroll
            for (int nt = 0; nt < 4; nt++) {
                const float* bb = Bs + (wn * 32 + nt * 8 + g) * KC;
                b[nt][0] = __float_as_uint(bb[w0]);
                b[nt][1] = __float_as_uint(bb[w1]);
            }
#pragma unroll
            for (int mt = 0; mt < 4; mt++)
#pragma unroll
                for (int nt = 0; nt < 4; nt++)
                    mma_tf32(acc[mt][nt], a[mt], b[nt]);
        }
        __syncthreads();
        buf ^= 1;
    }

    // ---- fused selection epilogue ----
    // thread owns rows R(mt,h) = wm*64+mt*16+g+8h (8 rows), cols wn*32+nt*8+2q+e
    float pS[4][2], nS[4][2];
    int   pI[4][2], nI[4][2];
#pragma unroll
    for (int mt = 0; mt < 4; mt++)
#pragma unroll
        for (int h = 0; h < 2; h++) {
            int r = wm * 64 + mt * 16 + g + 8 * h;
            int gi = i0 + r;
            int li = Li[r];
            float ps = POS_INF, ns = NEG_INF;
            int pi = 0x7fffffff, ni = 0x7fffffff;
#pragma unroll
            for (int nt = 0; nt < 4; nt++)
#pragma unroll
                for (int e = 0; e < 2; e++) {
                    int col = wn * 32 + nt * 8 + 2 * q + e;
                    int gj = j0 + col;
                    float s = acc[mt][nt][h * 2 + e];
                    if (Lj[col] == li) {
                        if (gj != gi && (s < ps || (s == ps && gj < pi))) { ps = s; pi = gj; }
                    } else if (s > ns || (s == ns && gj < ni)) { ns = s; ni = gj; }
                }
            pS[mt][h] = ps; pI[mt][h] = pi;
            nS[mt][h] = ns; nI[mt][h] = ni;
        }

    // reduce across the 4 lanes (q) of each quad
#pragma unroll
    for (int mt = 0; mt < 4; mt++)
#pragma unroll
        for (int h = 0; h < 2; h++) {
#pragma unroll
            for (int o = 1; o <= 2; o <<= 1) {
                float ops = __shfl_xor_sync(0xffffffffu, pS[mt][h], o);
                int   opi = __shfl_xor_sync(0xffffffffu, pI[mt][h], o);
                float ons = __shfl_xor_sync(0xffffffffu, nS[mt][h], o);
                int   oni = __shfl_xor_sync(0xffffffffu, nI[mt][h], o);
                if (ops < pS[mt][h] || (ops == pS[mt][h] && opi < pI[mt][h])) {
                    pS[mt][h] = ops; pI[mt][h] = opi;
                }
                if (ons > nS[mt][h] || (ons == nS[mt][h] && oni < nI[mt][h])) {
                    nS[mt][h] = ons; nI[mt][h] = oni;
                }
            }
        }

    __syncthreads();   // buffers dead; overlay epilogue arrays
    float* ePS = (float*)(smem + S_EPS);
    int*   ePI = (int*)(smem + S_EPI);
    float* eNS = (float*)(smem + S_ENS);
    int*   eNI = (int*)(smem + S_ENI);
    if (q == 0) {
#pragma unroll
        for (int mt = 0; mt < 4; mt++)
#pragma unroll
            for (int h = 0; h < 2; h++) {
                int r = wm * 64 + mt * 16 + g + 8 * h;
                ePS[wn * 128 + r] = pS[mt][h];  ePI[wn * 128 + r] = pI[mt][h];
                eNS[wn * 128 + r] = nS[mt][h];  eNI[wn * 128 + r] = nI[mt][h];
            }
    }
    __syncthreads();
    if (t < 128) {
        float ps = POS_INF, ns = NEG_INF;
        int pi = 0x7fffffff, ni = 0x7fffffff;
#pragma unroll
        for (int nt = 0; nt < 4; nt++) {      // ascending j strips
            float cps = ePS[nt * 128 + t]; int cpi = ePI[nt * 128 + t];
            float cns = eNS[nt * 128 + t]; int cni = eNI[nt * 128 + t];
            if (cps < ps || (cps == ps && cpi < pi)) { ps = cps; pi = cpi; }
            if (cns > ns || (cns == ns && cni < ni)) { ns = cns; ni = cni; }
        }
        int gi = i0 + t;
        g_posSim[blockIdx.y][gi] = ps;  g_posIdx[blockIdx.y][gi] = pi;
        g_negSim[blockIdx.y][gi] = ns;  g_negIdx[blockIdx.y][gi] = ni;
    }
}

// ============================================================
// Kernel 3: combine chunk partials + exact fp32 triplet terms
// ============================================================
__global__ void loss_kernel(const float* __restrict__ emb) {
    int warp = (blockIdx.x * blockDim.x + threadIdx.x) >> 5;
    int lane = threadIdx.x & 31;
    if (warp >= NN) return;
    int i = warp;

    float ps = g_posSim[0][i]; int pi = g_posIdx[0][i];
    float ns = g_negSim[0][i]; int ni = g_negIdx[0][i];
#pragma unroll 8
    for (int c = 1; c < NCHUNK; c++) {
        float cps = g_posSim[c][i]; int cpi = g_posIdx[c][i];
        float cns = g_negSim[c][i]; int cni = g_negIdx[c][i];
        if (cps < ps || (cps == ps && cpi < pi)) { ps = cps; pi = cpi; }
        if (cns > ns || (cns == ns && cni < ni)) { ns = cns; ni = cni; }
    }
    bool hasP = (ps < POS_INF);
    bool hasN = (ns > NEG_INF);
    bool valid = hasP && hasN;
    if (!hasP) pi = 0;
    if (!hasN) ni = 0;

    const float* a = emb + (size_t)i * DD;
    const float* p = emb + (size_t)pi * DD;
    const float* g = emb + (size_t)ni * DD;
    float sap = 0.f, san = 0.f;
#pragma unroll
    for (int qq = 0; qq < 16; qq++) {
        int k = lane + 32 * qq;
        float dap = a[k] - p[k] + 1e-6f;
        float dan = a[k] - g[k] + 1e-6f;
        sap = fmaf(dap, dap, sap);
        san = fmaf(dan, dan, san);
    }
#pragma unroll
    for (int o = 16; o; o >>= 1) {
        sap += __shfl_xor_sync(0xffffffffu, sap, o);
        san += __shfl_xor_sync(0xffffffffu, san, o);
    }
    if (lane == 0) {
        float per = fmaxf(sqrtf(sap) - sqrtf(san) + 1.0f, 0.0f);
        g_per[i]    = valid ? per : 0.0f;
        g_validf[i] = valid ? 1.0f : 0.0f;
    }
}

// ============================================================
// Kernel 4: deterministic final reduction
// ============================================================
__global__ void reduce_kernel(float* __restrict__ out) {
    __shared__ float s1[1024];
    __shared__ float s2[1024];
    int t = threadIdx.x;
    float a = 0.f, b = 0.f;
    for (int i = t; i < NN; i += 1024) { a += g_per[i]; b += g_validf[i]; }
    s1[t] = a; s2[t] = b;
    __syncthreads();
#pragma unroll
    for (int o = 512; o; o >>= 1) {
        if (t < o) { s1[t] += s1[t + o]; s2[t] += s2[t + o]; }
        __syncthreads();
    }
    if (t == 0) out[0] = s1[0] / fmaxf(s2[0], 1.0f);
}

// ============================================================
extern "C" void kernel_launch(void* const* d_in, const int* in_sizes, int n_in,
                              void* d_out, int out_size) {
    const float* emb    = (const float*)d_in[0];
    const int*   labels = (const int*)d_in[1];
    float* out = (float*)d_out;

    cudaFuncSetAttribute(simtile_kernel,
                         cudaFuncAttributeMaxDynamicSharedMemorySize, S_TOTAL);

    normalize_kernel<<<NN / 8, 256>>>(emb);
    dim3 grid(NN / TMT, NN / TNT);          // 64 x 64
    simtile_kernel<<<grid, 256, S_TOTAL>>>(labels);
    loss_kernel<<<NN / 8, 256>>>(emb);
    reduce_kernel<<<1, 1024>>>(out);
}

// round 6
// speedup vs baseline: 7.1877x; 1.5767x over previous
#include <cuda_runtime.h>
#include <math.h>
#include <stdint.h>

#define NN 8192
#define DD 512
#define TMT 128                    // CTA tile M
#define TNT 128                    // CTA tile N
#define NCHUNK (NN / TNT)          // 64 column chunks
#define KC 32                      // K per pipeline chunk
#define NKC (DD / KC)              // 16

#define POS_INF  __int_as_float(0x7f800000)
#define NEG_INF  __int_as_float(0xff800000)

// smem layout (bytes)
#define S_LJ   0                   // 128 col labels
#define S_LI   512                 // 128 row labels
#define S_BUF  1024                // 2 x (A 16KB + B 16KB)
#define ABUF_BYTES (TMT * KC * 4)  // 16384
#define S_TOTAL (S_BUF + 2 * (2 * ABUF_BYTES))   // 66560
// epilogue overlays (reuse buffer region)
#define S_EPS  S_BUF               // float [4][128]  row partials per wn strip
#define S_EPI  (S_BUF + 2048)
#define S_ENS  (S_BUF + 4096)
#define S_ENI  (S_BUF + 6144)
#define S_CPS  (S_BUF + 8192)      // float [128]  col partials (wm=1)
#define S_CPI  (S_BUF + 8704)
#define S_CNS  (S_BUF + 9216)
#define S_CNI  (S_BUF + 9728)

// ---- device scratch ----
__device__ float g_unit[NN * DD];                 // tf32-rounded unit vectors
__device__ float g_posSim[NCHUNK][NN];
__device__ int   g_posIdx[NCHUNK][NN];
__device__ float g_negSim[NCHUNK][NN];
__device__ int   g_negIdx[NCHUNK][NN];
__device__ float g_red[NN / 8][2];                // per-loss-block partials

__device__ __forceinline__ uint32_t smem_u32(const void* p) {
    uint32_t a;
    asm("{ .reg .u64 t; cvta.to.shared.u64 t, %1; cvt.u32.u64 %0, t; }" : "=r"(a) : "l"(p));
    return a;
}
#define CP_ASYNC16(dst, src) \
    asm volatile("cp.async.cg.shared.global [%0], [%1], 16;" :: "r"(dst), "l"(src))
#define CP_COMMIT() asm volatile("cp.async.commit_group;" ::: "memory")
#define CP_WAIT(n)  asm volatile("cp.async.wait_group %0;" :: "n"(n) : "memory")

__device__ __forceinline__ void mma_tf32(float* d, const uint32_t* a, const uint32_t* b) {
    asm volatile(
        "mma.sync.aligned.m16n8k8.row.col.f32.tf32.tf32.f32 "
        "{%0,%1,%2,%3}, {%4,%5,%6,%7}, {%8,%9}, {%0,%1,%2,%3};"
        : "+f"(d[0]), "+f"(d[1]), "+f"(d[2]), "+f"(d[3])
        : "r"(a[0]), "r"(a[1]), "r"(a[2]), "r"(a[3]), "r"(b[0]), "r"(b[1]));
}

// ============================================================
// Kernel 1: unit = tf32_round(emb / max(||emb||, 1e-8))
// ============================================================
__global__ void normalize_kernel(const float* __restrict__ emb) {
    int warp = (blockIdx.x * blockDim.x + threadIdx.x) >> 5;
    int lane = threadIdx.x & 31;
    if (warp >= NN) return;
    const float* row = emb + (size_t)warp * DD;
    float v[16];
    float ss = 0.f;
#pragma unroll
    for (int q = 0; q < 16; q++) { v[q] = row[lane + 32 * q]; ss += v[q] * v[q]; }
#pragma unroll
    for (int o = 16; o; o >>= 1) ss += __shfl_xor_sync(0xffffffffu, ss, o);
    float inv = 1.0f / fmaxf(sqrtf(ss), 1e-8f);
#pragma unroll
    for (int q = 0; q < 16; q++) {
        uint32_t u;
        asm("cvt.rna.tf32.f32 %0, %1;" : "=r"(u) : "f"(v[q] * inv));
        g_unit[(size_t)warp * DD + lane + 32 * q] = __uint_as_float(u);
    }
}

// ============================================================
// Kernel 2: tf32 mma.sync Gram tile (128x128), upper-triangular tiles only,
// fused row-wise AND (transposed) column-wise hardest pos/neg selection.
// ============================================================
__device__ __forceinline__ void load_chunk(char* smem, int buf,
                                           const float* Ab, const float* Bb,
                                           int kc, int t) {
    float* As = (float*)(smem + S_BUF + buf * 2 * ABUF_BYTES);
    float* Bs = As + TMT * KC;
#pragma unroll
    for (int p = 0; p < 4; p++) {
        int id = t + p * 256;
        int row = id >> 3, seg = id & 7;
        int dseg = seg ^ (row & 7);
        uint32_t dst = smem_u32(As + row * KC + dseg * 4);
        const char* src = (const char*)(Ab + (size_t)row * DD + kc * KC + seg * 4);
        CP_ASYNC16(dst, src);
    }
#pragma unroll
    for (int p = 0; p < 4; p++) {
        int id = t + p * 256;
        int row = id >> 3, seg = id & 7;
        int dseg = seg ^ (row & 7);
        uint32_t dst = smem_u32(Bs + row * KC + dseg * 4);
        const char* src = (const char*)(Bb + (size_t)row * DD + kc * KC + seg * 4);
        CP_ASYNC16(dst, src);
    }
    CP_COMMIT();
}

__global__ __launch_bounds__(256, 2)
void simtile_kernel(const int* __restrict__ labels) {
    const int bi = blockIdx.x, bj = blockIdx.y;
    if (bj < bi) return;                      // symmetric: upper triangle only
    extern __shared__ char smem[];
    const int t = threadIdx.x;
    const int wid = t >> 5, lane = t & 31;
    const int wm = wid >> 2;          // 0..1  (64 rows each)
    const int wn = wid & 3;           // 0..3  (32 cols each)
    const int g = lane >> 2, q = lane & 3;
    const int i0 = bi * TMT;
    const int j0 = bj * TNT;

    int* Lj = (int*)(smem + S_LJ);
    int* Li = (int*)(smem + S_LI);
    if (t < 128) { Lj[t] = labels[j0 + t]; Li[t] = labels[i0 + t]; }

    const float* Ab = g_unit + (size_t)i0 * DD;
    const float* Bb = g_unit + (size_t)j0 * DD;

    float acc[4][4][4];
#pragma unroll
    for (int mt = 0; mt < 4; mt++)
#pragma unroll
        for (int nt = 0; nt < 4; nt++)
#pragma unroll
            for (int e = 0; e < 4; e++) acc[mt][nt][e] = 0.f;

    load_chunk(smem, 0, Ab, Bb, 0, t);

    int buf = 0;
#pragma unroll 1
    for (int kc = 0; kc < NKC; kc++) {
        if (kc + 1 < NKC) load_chunk(smem, buf ^ 1, Ab, Bb, kc + 1, t);
        if (kc + 1 < NKC) { CP_WAIT(1); } else { CP_WAIT(0); }
        __syncthreads();

        const float* As = (const float*)(smem + S_BUF + buf * 2 * ABUF_BYTES);
        const float* Bs = As + TMT * KC;
#pragma unroll
        for (int ks8 = 0; ks8 < 4; ks8++) {
            const int w0 = ((2 * ks8 + 0) ^ g) * 4 + q;
            const int w1 = ((2 * ks8 + 1) ^ g) * 4 + q;
            uint32_t a[4][4], b[4][2];
#pragma unroll
            for (int mt = 0; mt < 4; mt++) {
                const float* b0 = As + (wm * 64 + mt * 16 + g) * KC;
                const float* b1 = b0 + 8 * KC;
                a[mt][0] = __float_as_uint(b0[w0]);
                a[mt][1] = __float_as_uint(b1[w0]);
                a[mt][2] = __float_as_uint(b0[w1]);
                a[mt][3] = __float_as_uint(b1[w1]);
            }
#pragma unroll
            for (int nt = 0; nt < 4; nt++) {
                const float* bb = Bs + (wn * 32 + nt * 8 + g) * KC;
                b[nt][0] = __float_as_uint(bb[w0]);
                b[nt][1] = __float_as_uint(bb[w1]);
            }
#pragma unroll
            for (int mt = 0; mt < 4; mt++)
#pragma unroll
                for (int nt = 0; nt < 4; nt++)
                    mma_tf32(acc[mt][nt], a[mt], b[nt]);
        }
        __syncthreads();
        buf ^= 1;
    }

    // ======== row-wise selection (rows of bi over cols chunk bj) ========
    float pS[4][2], nS[4][2];
    int   pI[4][2], nI[4][2];
#pragma unroll
    for (int mt = 0; mt < 4; mt++)
#pragma unroll
        for (int h = 0; h < 2; h++) {
            int r = wm * 64 + mt * 16 + g + 8 * h;
            int gi = i0 + r;
            int li = Li[r];
            float ps = POS_INF, ns = NEG_INF;
            int pi = 0x7fffffff, ni = 0x7fffffff;
#pragma unroll
            for (int nt = 0; nt < 4; nt++)
#pragma unroll
                for (int e = 0; e < 2; e++) {
                    int col = wn * 32 + nt * 8 + 2 * q + e;
                    int gj = j0 + col;
                    float s = acc[mt][nt][h * 2 + e];
                    if (Lj[col] == li) {
                        if (gj != gi && (s < ps || (s == ps && gj < pi))) { ps = s; pi = gj; }
                    } else if (s > ns || (s == ns && gj < ni)) { ns = s; ni = gj; }
                }
            pS[mt][h] = ps; pI[mt][h] = pi;
            nS[mt][h] = ns; nI[mt][h] = ni;
        }
    // reduce across the 4 lanes (q) of each quad
#pragma unroll
    for (int mt = 0; mt < 4; mt++)
#pragma unroll
        for (int h = 0; h < 2; h++) {
#pragma unroll
            for (int o = 1; o <= 2; o <<= 1) {
                float ops = __shfl_xor_sync(0xffffffffu, pS[mt][h], o);
                int   opi = __shfl_xor_sync(0xffffffffu, pI[mt][h], o);
                float ons = __shfl_xor_sync(0xffffffffu, nS[mt][h], o);
                int   oni = __shfl_xor_sync(0xffffffffu, nI[mt][h], o);
                if (ops < pS[mt][h] || (ops == pS[mt][h] && opi < pI[mt][h])) {
                    pS[mt][h] = ops; pI[mt][h] = opi;
                }
                if (ons > nS[mt][h] || (ons == nS[mt][h] && oni < nI[mt][h])) {
                    nS[mt][h] = ons; nI[mt][h] = oni;
                }
            }
        }

    // ======== column-wise selection (rows of bj over cols chunk bi) ========
    const bool offdiag = (bi != bj);
    float cpS[4][2], cnS[4][2];
    int   cpI[4][2], cnI[4][2];
    if (offdiag) {
#pragma unroll
        for (int nt = 0; nt < 4; nt++)
#pragma unroll
            for (int e = 0; e < 2; e++) {
                int col = wn * 32 + nt * 8 + 2 * q + e;
                int lj = Lj[col];
                float ps = POS_INF, ns = NEG_INF;
                int pi = 0x7fffffff, ni = 0x7fffffff;
#pragma unroll
                for (int mt = 0; mt < 4; mt++)
#pragma unroll
                    for (int h = 0; h < 2; h++) {
                        int r = wm * 64 + mt * 16 + g + 8 * h;
                        int gi2 = i0 + r;                 // candidate index (i side)
                        float s = acc[mt][nt][h * 2 + e];
                        if (Li[r] == lj) {                // bi != bj -> never self
                            if (s < ps || (s == ps && gi2 < pi)) { ps = s; pi = gi2; }
                        } else if (s > ns || (s == ns && gi2 < ni)) { ns = s; ni = gi2; }
                    }
                cpS[nt][e] = ps; cpI[nt][e] = pi;
                cnS[nt][e] = ns; cnI[nt][e] = ni;
            }
        // reduce across g (lane bits 2..4); same-col lanes share q
#pragma unroll
        for (int nt = 0; nt < 4; nt++)
#pragma unroll
            for (int e = 0; e < 2; e++) {
#pragma unroll
                for (int o = 4; o <= 16; o <<= 1) {
                    float ops = __shfl_xor_sync(0xffffffffu, cpS[nt][e], o);
                    int   opi = __shfl_xor_sync(0xffffffffu, cpI[nt][e], o);
                    float ons = __shfl_xor_sync(0xffffffffu, cnS[nt][e], o);
                    int   oni = __shfl_xor_sync(0xffffffffu, cnI[nt][e], o);
                    if (ops < cpS[nt][e] || (ops == cpS[nt][e] && opi < cpI[nt][e])) {
                        cpS[nt][e] = ops; cpI[nt][e] = opi;
                    }
                    if (ons > cnS[nt][e] || (ons == cnS[nt][e] && oni < cnI[nt][e])) {
                        cnS[nt][e] = ons; cnI[nt][e] = oni;
                    }
                }
            }
    }

    __syncthreads();   // mainloop buffers dead; overlay epilogue arrays
    float* ePS = (float*)(smem + S_EPS);
    int*   ePI = (int*)(smem + S_EPI);
    float* eNS = (float*)(smem + S_ENS);
    int*   eNI = (int*)(smem + S_ENI);
    if (q == 0) {
#pragma unroll
        for (int mt = 0; mt < 4; mt++)
#pragma unroll
            for (int h = 0; h < 2; h++) {
                int r = wm * 64 + mt * 16 + g + 8 * h;
                ePS[wn * 128 + r] = pS[mt][h];  ePI[wn * 128 + r] = pI[mt][h];
                eNS[wn * 128 + r] = nS[mt][h];  eNI[wn * 128 + r] = nI[mt][h];
            }
    }
    if (offdiag && g == 0 && wm == 1) {
        float* cPS = (float*)(smem + S_CPS);
        int*   cPI = (int*)(smem + S_CPI);
        float* cNS = (float*)(smem + S_CNS);
        int*   cNI = (int*)(smem + S_CNI);
#pragma unroll
        for (int nt = 0; nt < 4; nt++)
#pragma unroll
            for (int e = 0; e < 2; e++) {
                int col = wn * 32 + nt * 8 + 2 * q + e;
                cPS[col] = cpS[nt][e];  cPI[col] = cpI[nt][e];
                cNS[col] = cnS[nt][e];  cNI[col] = cnI[nt][e];
            }
    }
    __syncthreads();
    if (t < 128) {
        float ps = POS_INF, ns = NEG_INF;
        int pi = 0x7fffffff, ni = 0x7fffffff;
#pragma unroll
        for (int nt = 0; nt < 4; nt++) {
            float cps = ePS[nt * 128 + t]; int cpi = ePI[nt * 128 + t];
            float cns = eNS[nt * 128 + t]; int cni = eNI[nt * 128 + t];
            if (cps < ps || (cps == ps && cpi < pi)) { ps = cps; pi = cpi; }
            if (cns > ns || (cns == ns && cni < ni)) { ns = cns; ni = cni; }
        }
        int gi = i0 + t;
        g_posSim[bj][gi] = ps;  g_posIdx[bj][gi] = pi;
        g_negSim[bj][gi] = ns;  g_negIdx[bj][gi] = ni;
    }
    if (offdiag && g == 0 && wm == 0) {
        const float* cPS = (const float*)(smem + S_CPS);
        const int*   cPI = (const int*)(smem + S_CPI);
        const float* cNS = (const float*)(smem + S_CNS);
        const int*   cNI = (const int*)(smem + S_CNI);
#pragma unroll
        for (int nt = 0; nt < 4; nt++)
#pragma unroll
            for (int e = 0; e < 2; e++) {
                int col = wn * 32 + nt * 8 + 2 * q + e;
                float ps = cpS[nt][e]; int pi = cpI[nt][e];
                float ns = cnS[nt][e]; int ni = cnI[nt][e];
                float ops = cPS[col]; int opi = cPI[col];
                float ons = cNS[col]; int oni = cNI[col];
                if (ops < ps || (ops == ps && opi < pi)) { ps = ops; pi = opi; }
                if (ons > ns || (ons == ns && oni < ni)) { ns = ons; ni = oni; }
                int gj = j0 + col;
                g_posSim[bi][gj] = ps;  g_posIdx[bi][gj] = pi;
                g_negSim[bi][gj] = ns;  g_negIdx[bi][gj] = ni;
            }
    }
}

// ============================================================
// Kernel 3: combine chunk partials + exact fp32 triplet terms
// + block-level partial reduction (8 rows/block)
// ============================================================
__global__ void loss_kernel(const float* __restrict__ emb) {
    __shared__ float sred[8][2];
    int wib = threadIdx.x >> 5;                 // warp in block (0..7)
    int i = blockIdx.x * 8 + wib;
    int lane = threadIdx.x & 31;

    float ps = g_posSim[0][i]; int pi = g_posIdx[0][i];
    float ns = g_negSim[0][i]; int ni = g_negIdx[0][i];
#pragma unroll 8
    for (int c = 1; c < NCHUNK; c++) {
        float cps = g_posSim[c][i]; int cpi = g_posIdx[c][i];
        float cns = g_negSim[c][i]; int cni = g_negIdx[c][i];
        if (cps < ps || (cps == ps && cpi < pi)) { ps = cps; pi = cpi; }
        if (cns > ns || (cns == ns && cni < ni)) { ns = cns; ni = cni; }
    }
    bool hasP = (ps < POS_INF);
    bool hasN = (ns > NEG_INF);
    bool valid = hasP && hasN;
    if (!hasP) pi = 0;
    if (!hasN) ni = 0;

    const float* a = emb + (size_t)i * DD;
    const float* p = emb + (size_t)pi * DD;
    const float* g = emb + (size_t)ni * DD;
    float sap = 0.f, san = 0.f;
#pragma unroll
    for (int qq = 0; qq < 16; qq++) {
        int k = lane + 32 * qq;
        float dap = a[k] - p[k] + 1e-6f;
        float dan = a[k] - g[k] + 1e-6f;
        sap = fmaf(dap, dap, sap);
        san = fmaf(dan, dan, san);
    }
#pragma unroll
    for (int o = 16; o; o >>= 1) {
        sap += __shfl_xor_sync(0xffffffffu, sap, o);
        san += __shfl_xor_sync(0xffffffffu, san, o);
    }
    if (lane == 0) {
        float per = fmaxf(sqrtf(sap) - sqrtf(san) + 1.0f, 0.0f);
        sred[wib][0] = valid ? per : 0.0f;
        sred[wib][1] = valid ? 1.0f : 0.0f;
    }
    __syncthreads();
    if (threadIdx.x == 0) {
        float sp = 0.f, sv = 0.f;
#pragma unroll
        for (int w = 0; w < 8; w++) { sp += sred[w][0]; sv += sred[w][1]; }
        g_red[blockIdx.x][0] = sp;
        g_red[blockIdx.x][1] = sv;
    }
}

// ============================================================
// Kernel 4: deterministic final reduction over 1024 block partials
// ============================================================
__global__ void reduce_kernel(float* __restrict__ out) {
    __shared__ float s1[1024];
    __shared__ float s2[1024];
    int t = threadIdx.x;
    s1[t] = g_red[t][0];
    s2[t] = g_red[t][1];
    __syncthreads();
#pragma unroll
    for (int o = 512; o; o >>= 1) {
        if (t < o) { s1[t] += s1[t + o]; s2[t] += s2[t + o]; }
        __syncthreads();
    }
    if (t == 0) out[0] = s1[0] / fmaxf(s2[0], 1.0f);
}

// ============================================================
extern "C" void kernel_launch(void* const* d_in, const int* in_sizes, int n_in,
                              void* d_out, int out_size) {
    const float* emb    = (const float*)d_in[0];
    const int*   labels = (const int*)d_in[1];
    float* out = (float*)d_out;

    cudaFuncSetAttribute(simtile_kernel,
                         cudaFuncAttributeMaxDynamicSharedMemorySize, S_TOTAL);

    normalize_kernel<<<NN / 8, 256>>>(emb);
    dim3 grid(NN / TMT, NN / TNT);          // 64 x 64, lower triangle exits early
    simtile_kernel<<<grid, 256, S_TOTAL>>>(labels);
    loss_kernel<<<NN / 8, 256>>>(emb);
    reduce_kernel<<<1, 1024>>>(out);
}

// round 9
// speedup vs baseline: 10.5842x; 1.4726x over previous
#include <cuda_runtime.h>
#include <cuda_fp16.h>
#include <math.h>
#include <stdint.h>

#define NN 8192
#define DD 512
#define TMT 128                    // CTA tile M
#define TNT 128                    // CTA tile N
#define NCHUNK (NN / TNT)          // 64 column chunks
#define KC 64                      // K per pipeline chunk (fp16: 128B/row)
#define NKC (DD / KC)              // 8

#define POS_INF  __int_as_float(0x7f800000)
#define NEG_INF  __int_as_float(0xff800000)

// smem layout (bytes)
#define S_LJ   0                   // 128 col labels
#define S_LI   512                 // 128 row labels
#define S_BUF  1024
#define ABUF_BYTES (TMT * KC * 2)  // 16384 (fp16)
#define S_TOTAL (S_BUF + 2 * (2 * ABUF_BYTES))   // 66560
// epilogue overlays (reuse buffer region)
#define S_EPS  S_BUF               // float [4][128]  row partials per wn strip
#define S_EPI  (S_BUF + 2048)
#define S_ENS  (S_BUF + 4096)
#define S_ENI  (S_BUF + 6144)
#define S_CPS  (S_BUF + 8192)      // float [128]  col partials (wm=1)
#define S_CPI  (S_BUF + 8704)
#define S_CNS  (S_BUF + 9216)
#define S_CNI  (S_BUF + 9728)

// ---- device scratch ----
__device__ __half g_unit[NN * DD];                // fp16 unit vectors (8 MB)
__device__ float g_posSim[NCHUNK][NN];
__device__ int   g_posIdx[NCHUNK][NN];
__device__ float g_negSim[NCHUNK][NN];
__device__ int   g_negIdx[NCHUNK][NN];
__device__ float g_red[NN / 8][2];                // per-loss-block partials

__device__ __forceinline__ uint32_t smem_u32(const void* p) {
    uint32_t a;
    asm("{ .reg .u64 t; cvta.to.shared.u64 t, %1; cvt.u32.u64 %0, t; }" : "=r"(a) : "l"(p));
    return a;
}
#define CP_ASYNC16(dst, src) \
    asm volatile("cp.async.cg.shared.global [%0], [%1], 16;" :: "r"(dst), "l"(src))
#define CP_COMMIT() asm volatile("cp.async.commit_group;" ::: "memory")
#define CP_WAIT(n)  asm volatile("cp.async.wait_group %0;" :: "n"(n) : "memory")

__device__ __forceinline__ void ldm_x4(uint32_t* r, uint32_t addr) {
    asm volatile("ldmatrix.sync.aligned.m8n8.x4.shared.b16 {%0,%1,%2,%3}, [%4];"
        : "=r"(r[0]), "=r"(r[1]), "=r"(r[2]), "=r"(r[3]) : "r"(addr));
}
__device__ __forceinline__ void mma_f16(float* d, const uint32_t* a, const uint32_t* b) {
    asm volatile(
        "mma.sync.aligned.m16n8k16.row.col.f32.f16.f16.f32 "
        "{%0,%1,%2,%3}, {%4,%5,%6,%7}, {%8,%9}, {%0,%1,%2,%3};"
        : "+f"(d[0]), "+f"(d[1]), "+f"(d[2]), "+f"(d[3])
        : "r"(a[0]), "r"(a[1]), "r"(a[2]), "r"(a[3]), "r"(b[0]), "r"(b[1]));
}

// ============================================================
// Kernel 1: unit = fp16_round(emb / max(||emb||, 1e-8))
// ============================================================
__global__ void normalize_kernel(const float* __restrict__ emb) {
    int warp = (blockIdx.x * blockDim.x + threadIdx.x) >> 5;
    int lane = threadIdx.x & 31;
    if (warp >= NN) return;
    const float* row = emb + (size_t)warp * DD;
    float v[16];
    float ss = 0.f;
#pragma unroll
    for (int q = 0; q < 16; q++) { v[q] = row[lane + 32 * q]; ss += v[q] * v[q]; }
#pragma unroll
    for (int o = 16; o; o >>= 1) ss += __shfl_xor_sync(0xffffffffu, ss, o);
    float inv = 1.0f / fmaxf(sqrtf(ss), 1e-8f);
#pragma unroll
    for (int q = 0; q < 16; q++)
        g_unit[(size_t)warp * DD + lane + 32 * q] = __float2half_rn(v[q] * inv);
}

// ============================================================
// Kernel 2: fp16 mma.sync Gram tile (128x128), upper-triangular tiles only,
// fused row-wise AND (transposed) column-wise hardest pos/neg selection.
// SMEM tile rows: 128B (64 fp16), XOR-8 swizzle on 16B granules.
// ============================================================
__device__ __forceinline__ void load_chunk(char* smem, int buf,
                                           const __half* Ab, const __half* Bb,
                                           int kc, int t) {
    char* As = smem + S_BUF + buf * 2 * ABUF_BYTES;
    char* Bs = As + ABUF_BYTES;
#pragma unroll
    for (int p = 0; p < 4; p++) {
        int id = t + p * 256;
        int row = id >> 3, c = id & 7;
        int dc = c ^ (row & 7);
        uint32_t dst = smem_u32(As + row * 128 + dc * 16);
        const char* src = (const char*)Ab + (size_t)row * (DD * 2) + kc * 128 + c * 16;
        CP_ASYNC16(dst, src);
    }
#pragma unroll
    for (int p = 0; p < 4; p++) {
        int id = t + p * 256;
        int row = id >> 3, c = id & 7;
        int dc = c ^ (row & 7);
        uint32_t dst = smem_u32(Bs + row * 128 + dc * 16);
        const char* src = (const char*)Bb + (size_t)row * (DD * 2) + kc * 128 + c * 16;
        CP_ASYNC16(dst, src);
    }
    CP_COMMIT();
}

__global__ __launch_bounds__(256, 2)
void simtile_kernel(const int* __restrict__ labels) {
    const int bi = blockIdx.x, bj = blockIdx.y;
    if (bj < bi) return;                      // symmetric: upper triangle only
    extern __shared__ char smem[];
    const int t = threadIdx.x;
    const int wid = t >> 5, lane = t & 31;
    const int wm = wid >> 2;          // 0..1  (64 rows each)
    const int wn = wid & 3;           // 0..3  (32 cols each)
    const int g = lane >> 2, q = lane & 3;
    const int i0 = bi * TMT;
    const int j0 = bj * TNT;

    int* Lj = (int*)(smem + S_LJ);
    int* Li = (int*)(smem + S_LI);
    if (t < 128) { Lj[t] = labels[j0 + t]; Li[t] = labels[i0 + t]; }

    const __half* Ab = g_unit + (size_t)i0 * DD;
    const __half* Bb = g_unit + (size_t)j0 * DD;

    // ldmatrix per-lane address invariants
    const int m8 = lane >> 3, rw = lane & 7;
    // A: r0=rows0-7 kh0, r1=rows8-15 kh0, r2=rows0-7 kh1, r3=rows8-15 kh1
    const uint32_t aRowOff = (uint32_t)(wm * 64 + (m8 & 1) * 8 + rw) * 128;
    const int aKh = m8 >> 1;
    // B: r0=(nt)kh0, r1=(nt)kh1, r2=(nt+1)kh0, r3=(nt+1)kh1
    const uint32_t bRowOff = (uint32_t)(wn * 32 + (m8 >> 1) * 8 + rw) * 128;
    const int bKh = m8 & 1;

    float acc[4][4][4];
#pragma unroll
    for (int mt = 0; mt < 4; mt++)
#pragma unroll
        for (int nt = 0; nt < 4; nt++)
#pragma unroll
            for (int e = 0; e < 4; e++) acc[mt][nt][e] = 0.f;

    load_chunk(smem, 0, Ab, Bb, 0, t);

    int buf = 0;
#pragma unroll 1
    for (int kc = 0; kc < NKC; kc++) {
        if (kc + 1 < NKC) load_chunk(smem, buf ^ 1, Ab, Bb, kc + 1, t);
        if (kc + 1 < NKC) { CP_WAIT(1); } else { CP_WAIT(0); }
        __syncthreads();

        const uint32_t sA = smem_u32(smem + S_BUF + buf * 2 * ABUF_BYTES);
        const uint32_t sB = sA + ABUF_BYTES;
#pragma unroll
        for (int ks = 0; ks < 4; ks++) {      // 4 x k16 per chunk
            uint32_t a[4][4], bfr[4][2];
            const uint32_t aG = (uint32_t)(((ks * 2 + aKh) ^ rw) << 4);
            const uint32_t bG = (uint32_t)(((ks * 2 + bKh) ^ rw) << 4);
#pragma unroll
            for (int mt = 0; mt < 4; mt++)
                ldm_x4(a[mt], sA + aRowOff + (uint32_t)mt * 2048 + aG);
#pragma unroll
            for (int n2 = 0; n2 < 2; n2++) {
                uint32_t r[4];
                ldm_x4(r, sB + bRowOff + (uint32_t)n2 * 2048 + bG);
                bfr[n2 * 2 + 0][0] = r[0]; bfr[n2 * 2 + 0][1] = r[1];
                bfr[n2 * 2 + 1][0] = r[2]; bfr[n2 * 2 + 1][1] = r[3];
            }
#pragma unroll
            for (int mt = 0; mt < 4; mt++)
#pragma unroll
                for (int nt = 0; nt < 4; nt++)
                    mma_f16(acc[mt][nt], a[mt], bfr[nt]);
        }
        __syncthreads();
        buf ^= 1;
    }

    // ======== row-wise selection (rows of bi over cols chunk bj) ========
    float pS[4][2], nS[4][2];
    int   pI[4][2], nI[4][2];
#pragma unroll
    for (int mt = 0; mt < 4; mt++)
#pragma unroll
        for (int h = 0; h < 2; h++) {
            int r = wm * 64 + mt * 16 + g + 8 * h;
            int gi = i0 + r;
            int li = Li[r];
            float ps = POS_INF, ns = NEG_INF;
            int pi = 0x7fffffff, ni = 0x7fffffff;
#pragma unroll
            for (int nt = 0; nt < 4; nt++)
#pragma unroll
                for (int e = 0; e < 2; e++) {
                    int col = wn * 32 + nt * 8 + 2 * q + e;
                    int gj = j0 + col;
                    float s = acc[mt][nt][h * 2 + e];
                    if (Lj[col] == li) {
                        if (gj != gi && (s < ps || (s == ps && gj < pi))) { ps = s; pi = gj; }
                    } else if (s > ns || (s == ns && gj < ni)) { ns = s; ni = gj; }
                }
            pS[mt][h] = ps; pI[mt][h] = pi;
            nS[mt][h] = ns; nI[mt][h] = ni;
        }
#pragma unroll
    for (int mt = 0; mt < 4; mt++)
#pragma unroll
        for (int h = 0; h < 2; h++) {
#pragma unroll
            for (int o = 1; o <= 2; o <<= 1) {
                float ops = __shfl_xor_sync(0xffffffffu, pS[mt][h], o);
                int   opi = __shfl_xor_sync(0xffffffffu, pI[mt][h], o);
                float ons = __shfl_xor_sync(0xffffffffu, nS[mt][h], o);
                int   oni = __shfl_xor_sync(0xffffffffu, nI[mt][h], o);
                if (ops < pS[mt][h] || (ops == pS[mt][h] && opi < pI[mt][h])) {
                    pS[mt][h] = ops; pI[mt][h] = opi;
                }
                if (ons > nS[mt][h] || (ons == nS[mt][h] && oni < nI[mt][h])) {
                    nS[mt][h] = ons; nI[mt][h] = oni;
                }
            }
        }

    // ======== column-wise selection (rows of bj over cols chunk bi) ========
    const bool offdiag = (bi != bj);
    float cpS[4][2], cnS[4][2];
    int   cpI[4][2], cnI[4][2];
    if (offdiag) {
#pragma unroll
        for (int nt = 0; nt < 4; nt++)
#pragma unroll
            for (int e = 0; e < 2; e++) {
                int col = wn * 32 + nt * 8 + 2 * q + e;
                int lj = Lj[col];
                float ps = POS_INF, ns = NEG_INF;
                int pi = 0x7fffffff, ni = 0x7fffffff;
#pragma unroll
                for (int mt = 0; mt < 4; mt++)
#pragma unroll
                    for (int h = 0; h < 2; h++) {
                        int r = wm * 64 + mt * 16 + g + 8 * h;
                        int gi2 = i0 + r;
                        float s = acc[mt][nt][h * 2 + e];
                        if (Li[r] == lj) {
                            if (s < ps || (s == ps && gi2 < pi)) { ps = s; pi = gi2; }
                        } else if (s > ns || (s == ns && gi2 < ni)) { ns = s; ni = gi2; }
                    }
                cpS[nt][e] = ps; cpI[nt][e] = pi;
                cnS[nt][e] = ns; cnI[nt][e] = ni;
            }
#pragma unroll
        for (int nt = 0; nt < 4; nt++)
#pragma unroll
            for (int e = 0; e < 2; e++) {
#pragma unroll
                for (int o = 4; o <= 16; o <<= 1) {
                    float ops = __shfl_xor_sync(0xffffffffu, cpS[nt][e], o);
                    int   opi = __shfl_xor_sync(0xffffffffu, cpI[nt][e], o);
                    float ons = __shfl_xor_sync(0xffffffffu, cnS[nt][e], o);
                    int   oni = __shfl_xor_sync(0xffffffffu, cnI[nt][e], o);
                    if (ops < cpS[nt][e] || (ops == cpS[nt][e] && opi < cpI[nt][e])) {
                        cpS[nt][e] = ops; cpI[nt][e] = opi;
                    }
                    if (ons > cnS[nt][e] || (ons == cnS[nt][e] && oni < cnI[nt][e])) {
                        cnS[nt][e] = ons; cnI[nt][e] = oni;
                    }
                }
            }
    }

    __syncthreads();   // mainloop buffers dead; overlay epilogue arrays
    float* ePS = (float*)(smem + S_EPS);
    int*   ePI = (int*)(smem + S_EPI);
    float* eNS = (float*)(smem + S_ENS);
    int*   eNI = (int*)(smem + S_ENI);
    if (q == 0) {
#pragma unroll
        for (int mt = 0; mt < 4; mt++)
#pragma unroll
            for (int h = 0; h < 2; h++) {
                int r = wm * 64 + mt * 16 + g + 8 * h;
                ePS[wn * 128 + r] = pS[mt][h];  ePI[wn * 128 + r] = pI[mt][h];
                eNS[wn * 128 + r] = nS[mt][h];  eNI[wn * 128 + r] = nI[mt][h];
            }
    }
    if (offdiag && g == 0 && wm == 1) {
        float* cPS = (float*)(smem + S_CPS);
        int*   cPI = (int*)(smem + S_CPI);
        float* cNS = (float*)(smem + S_CNS);
        int*   cNI = (int*)(smem + S_CNI);
#pragma unroll
        for (int nt = 0; nt < 4; nt++)
#pragma unroll
            for (int e = 0; e < 2; e++) {
                int col = wn * 32 + nt * 8 + 2 * q + e;
                cPS[col] = cpS[nt][e];  cPI[col] = cpI[nt][e];
                cNS[col] = cnS[nt][e];  cNI[col] = cnI[nt][e];
            }
    }
    __syncthreads();
    if (t < 128) {
        float ps = POS_INF, ns = NEG_INF;
        int pi = 0x7fffffff, ni = 0x7fffffff;
#pragma unroll
        for (int nt = 0; nt < 4; nt++) {
            float cps = ePS[nt * 128 + t]; int cpi = ePI[nt * 128 + t];
            float cns = eNS[nt * 128 + t]; int cni = eNI[nt * 128 + t];
            if (cps < ps || (cps == ps && cpi < pi)) { ps = cps; pi = cpi; }
            if (cns > ns || (cns == ns && cni < ni)) { ns = cns; ni = cni; }
        }
        int gi = i0 + t;
        g_posSim[bj][gi] = ps;  g_posIdx[bj][gi] = pi;
        g_negSim[bj][gi] = ns;  g_negIdx[bj][gi] = ni;
    }
    if (offdiag && g == 0 && wm == 0) {
        const float* cPS = (const float*)(smem + S_CPS);
        const int*   cPI = (const int*)(smem + S_CPI);
        const float* cNS = (const float*)(smem + S_CNS);
        const int*   cNI = (const int*)(smem + S_CNI);
#pragma unroll
        for (int nt = 0; nt < 4; nt++)
#pragma unroll
            for (int e = 0; e < 2; e++) {
                int col = wn * 32 + nt * 8 + 2 * q + e;
                float ps = cpS[nt][e]; int pi = cpI[nt][e];
                float ns = cnS[nt][e]; int ni = cnI[nt][e];
                float ops = cPS[col]; int opi = cPI[col];
                float ons = cNS[col]; int oni = cNI[col];
                if (ops < ps || (ops == ps && opi < pi)) { ps = ops; pi = opi; }
                if (ons > ns || (ons == ns && oni < ni)) { ns = ons; ni = oni; }
                int gj = j0 + col;
                g_posSim[bi][gj] = ps;  g_posIdx[bi][gj] = pi;
                g_negSim[bi][gj] = ns;  g_negIdx[bi][gj] = ni;
            }
    }
}

// ============================================================
// Kernel 3: combine chunk partials + exact fp32 triplet terms
// + block-level partial reduction (8 rows/block)
// ============================================================
__global__ void loss_kernel(const float* __restrict__ emb) {
    __shared__ float sred[8][2];
    int wib = threadIdx.x >> 5;                 // warp in block (0..7)
    int i = blockIdx.x * 8 + wib;
    int lane = threadIdx.x & 31;

    float ps = g_posSim[0][i]; int pi = g_posIdx[0][i];
    float ns = g_negSim[0][i]; int ni = g_negIdx[0][i];
#pragma unroll 8
    for (int c = 1; c < NCHUNK; c++) {
        float cps = g_posSim[c][i]; int cpi = g_posIdx[c][i];
        float cns = g_negSim[c][i]; int cni = g_negIdx[c][i];
        if (cps < ps || (cps == ps && cpi < pi)) { ps = cps; pi = cpi; }
        if (cns > ns || (cns == ns && cni < ni)) { ns = cns; ni = cni; }
    }
    bool hasP = (ps < POS_INF);
    bool hasN = (ns > NEG_INF);
    bool valid = hasP && hasN;
    if (!hasP) pi = 0;
    if (!hasN) ni = 0;

    const float* a = emb + (size_t)i * DD;
    const float* p = emb + (size_t)pi * DD;
    const float* g = emb + (size_t)ni * DD;
    float sap = 0.f, san = 0.f;
#pragma unroll
    for (int qq = 0; qq < 16; qq++) {
        int k = lane + 32 * qq;
        float dap = a[k] - p[k] + 1e-6f;
        float dan = a[k] - g[k] + 1e-6f;
        sap = fmaf(dap, dap, sap);
        san = fmaf(dan, dan, san);
    }
#pragma unroll
    for (int o = 16; o; o >>= 1) {
        sap += __shfl_xor_sync(0xffffffffu, sap, o);
        san += __shfl_xor_sync(0xffffffffu, san, o);
    }
    if (lane == 0) {
        float per = fmaxf(sqrtf(sap) - sqrtf(san) + 1.0f, 0.0f);
        sred[wib][0] = valid ? per : 0.0f;
        sred[wib][1] = valid ? 1.0f : 0.0f;
    }
    __syncthreads();
    if (threadIdx.x == 0) {
        float sp = 0.f, sv = 0.f;
#pragma unroll
        for (int w = 0; w < 8; w++) { sp += sred[w][0]; sv += sred[w][1]; }
        g_red[blockIdx.x][0] = sp;
        g_red[blockIdx.x][1] = sv;
    }
}

// ============================================================
// Kernel 4: deterministic final reduction over 1024 block partials
// ============================================================
__global__ void reduce_kernel(float* __restrict__ out) {
    __shared__ float s1[1024];
    __shared__ float s2[1024];
    int t = threadIdx.x;
    s1[t] = g_red[t][0];
    s2[t] = g_red[t][1];
    __syncthreads();
#pragma unroll
    for (int o = 512; o; o >>= 1) {
        if (t < o) { s1[t] += s1[t + o]; s2[t] += s2[t + o]; }
        __syncthreads();
    }
    if (t == 0) out[0] = s1[0] / fmaxf(s2[0], 1.0f);
}

// ============================================================
extern "C" void kernel_launch(void* const* d_in, const int* in_sizes, int n_in,
                              void* d_out, int out_size) {
    const float* emb    = (const float*)d_in[0];
    const int*   labels = (const int*)d_in[1];
    float* out = (float*)d_out;

    cudaFuncSetAttribute(simtile_kernel,
                         cudaFuncAttributeMaxDynamicSharedMemorySize, S_TOTAL);

    normalize_kernel<<<NN / 8, 256>>>(emb);
    dim3 grid(NN / TMT, NN / TNT);          // 64 x 64, lower triangle exits early
    simtile_kernel<<<grid, 256, S_TOTAL>>>(labels);
    loss_kernel<<<NN / 8, 256>>>(emb);
    reduce_kernel<<<1, 1024>>>(out);
}